// round 12
// baseline (speedup 1.0000x reference)
#include <cuda_runtime.h>
#include <math.h>
#include <stdint.h>

#define D_MODEL   2048
#define Q_LATD    1536
#define KV_LATD   512
#define NUM_HEADS 16
#define HEAD_DIM  128
#define BATCH     2
#define SEQ       2048
#define ROWS      (BATCH * SEQ)      // 4096
#define QK_DIM    256                // head_dim(128) + rope(128)

// ---------------- scratch (device globals; no allocation allowed) ----------
__device__ float g_qlat[ROWS * Q_LATD];
__device__ float g_kvlat[ROWS * KV_LATD];
__device__ float g_qnew[(size_t)ROWS * NUM_HEADS * QK_DIM];   // [b,s,h,256] k-packed
__device__ float g_knew[(size_t)ROWS * NUM_HEADS * QK_DIM];   // [b,s,h,256] k-packed
__device__ float g_v[(size_t)ROWS * D_MODEL];                 // [b,s,h*128] v-packed
__device__ float g_attn[(size_t)ROWS * D_MODEL];
__device__ float g_qrt[(size_t)ROWS * D_MODEL];
__device__ float g_krt[(size_t)ROWS * HEAD_DIM];
// pre-rounded inputs + weights (tf32 bit patterns)
__device__ float g_rinq[(size_t)ROWS * D_MODEL];
__device__ float g_rink[(size_t)ROWS * D_MODEL];
__device__ float g_rWqd[(size_t)D_MODEL * Q_LATD];
__device__ float g_rWkvd[(size_t)D_MODEL * KV_LATD];
__device__ float g_rWqu[(size_t)Q_LATD * D_MODEL];
__device__ float g_rWqr[(size_t)Q_LATD * D_MODEL];
__device__ float g_rWku[(size_t)KV_LATD * D_MODEL];
__device__ float g_rWvu[(size_t)KV_LATD * D_MODEL];
__device__ float g_rWkr[(size_t)D_MODEL * HEAD_DIM];
__device__ float g_rWo[(size_t)D_MODEL * D_MODEL];

// ---------------- helpers --------------------------------------------------
__device__ __forceinline__ uint32_t f2tf(float x) {
    uint32_t u;
    asm("cvt.rna.tf32.f32 %0, %1;" : "=r"(u) : "f"(x));
    return u;
}

__device__ __forceinline__ uint32_t sptr(const void* p) {
    return (uint32_t)__cvta_generic_to_shared(p);
}

__device__ __forceinline__ void mma8(float c[4],
    uint32_t a0, uint32_t a1, uint32_t a2, uint32_t a3,
    uint32_t b0, uint32_t b1)
{
    asm volatile(
        "mma.sync.aligned.m16n8k8.row.col.f32.tf32.tf32.f32 "
        "{%0,%1,%2,%3}, {%4,%5,%6,%7}, {%8,%9}, {%0,%1,%2,%3};\n"
        : "+f"(c[0]), "+f"(c[1]), "+f"(c[2]), "+f"(c[3])
        : "r"(a0), "r"(a1), "r"(a2), "r"(a3), "r"(b0), "r"(b1));
}

__device__ __forceinline__ void ldmx4(uint32_t a[4], uint32_t addr) {
    asm volatile(
        "ldmatrix.sync.aligned.m8n8.x4.shared.b16 {%0,%1,%2,%3}, [%4];"
        : "=r"(a[0]), "=r"(a[1]), "=r"(a[2]), "=r"(a[3]) : "r"(addr));
}

#define CP16(dst, src) \
    asm volatile("cp.async.cg.shared.global [%0], [%1], 16;" :: "r"(dst), "l"(src))
#define CP_COMMIT() asm volatile("cp.async.commit_group;" ::: "memory")
#define CP_WAIT0()  asm volatile("cp.async.wait_group 0;" ::: "memory")

// exp(x) for x <= 0 on the FMA pipe only (no MUFU)
__device__ __forceinline__ float fast_exp(float x) {
    float y  = fmaxf(x * 1.4426950408889634f, -126.0f);
    float tb = y + 12582912.0f;
    float nf = tb - 12582912.0f;
    float u  = (y - nf) * 0.6931471805599453f;
    float p  = fmaf(u, 0.008333334f, 0.041666668f);
    p = fmaf(p, u, 0.16666667f);
    p = fmaf(p, u, 0.5f);
    p = fmaf(p, u, 1.0f);
    p = fmaf(p, u, 1.0f);
    return p * __int_as_float(((int)nf + 127) << 23);
}

// digit-swap within a 16-chunk: stored pos 4t+j holds original t+4j
__device__ __forceinline__ int permk(int k) {
    return (k & ~15) | (((k & 3) << 2) | ((k >> 2) & 3));
}

// ---------------- fused pre-round pass (float4 granularity) ----------------
#define RP1 2097152u
#define RP2 4194304u
#define RP3 4980736u
#define RP4 5242880u
#define RP5 6029312u
#define RP6 6815744u
#define RP7 7077888u
#define RP8 7340032u
#define RP9 7405568u
#define RPT 8454144u

__global__ void roundmany(
    const float* s0, float* d0, const float* s1, float* d1,
    const float* s2, float* d2, const float* s3, float* d3,
    const float* s4, float* d4, const float* s5, float* d5,
    const float* s6, float* d6, const float* s7, float* d7,
    const float* s8, float* d8, const float* s9, float* d9)
{
    uint32_t i = blockIdx.x * 256u + threadIdx.x;
    const float* s; float* d; uint32_t off;
    if      (i < RP1) { s = s0; d = d0; off = i; }
    else if (i < RP2) { s = s1; d = d1; off = i - RP1; }
    else if (i < RP3) { s = s2; d = d2; off = i - RP2; }
    else if (i < RP4) { s = s3; d = d3; off = i - RP3; }
    else if (i < RP5) { s = s4; d = d4; off = i - RP4; }
    else if (i < RP6) { s = s5; d = d5; off = i - RP5; }
    else if (i < RP7) { s = s6; d = d6; off = i - RP6; }
    else if (i < RP8) { s = s7; d = d7; off = i - RP7; }
    else if (i < RP9) { s = s8; d = d8; off = i - RP8; }
    else              { s = s9; d = d9; off = i - RP9; }
    float4 v = ((const float4*)s)[off];
    ((uint4*)d)[off] = make_uint4(f2tf(v.x), f2tf(v.y), f2tf(v.z), f2tf(v.w));
}

// ---------------- tf32 GEMM v5 (round-9/10 + oscale) -----------------------
#define GA16 2560
#define GB16 2176
#define GS_STG (2 * GA16 + 2 * GB16)        // 9472 words per 32-k stage
#define GEMM_SMEM_BYTES (2 * GS_STG * 4)    // 75776 B

__global__ void __launch_bounds__(256, 2) tf32gemm(
    const float* __restrict__ A, const float* __restrict__ B,
    float* __restrict__ C, const float* __restrict__ bias,
    int M, int N, int K, int ldc, int mode, int rnd, float oscale)
{
    extern __shared__ uint32_t sm[];
    const int tid = threadIdx.x, lane = tid & 31, w = tid >> 5;
    const int g = lane >> 2, t = lane & 3;
    const int wm = (w & 1) * 64, wn = (w >> 1) * 32;
    const int bm = blockIdx.y * 128, bn = blockIdx.x * 128;

    const int am = tid >> 1, ak = (tid & 1) * 8;
    const int bk = tid >> 4, bn0 = (tid & 15) * 8;
    const float* Ag = A + (size_t)(bm + am) * K + ak;
    const float* Bg = B + (size_t)bk * N + bn + bn0;

    const uint32_t smb = sptr(sm);
    const uint32_t aStg = smb + ((am * 20 + ak) << 2);
    const uint32_t bStg = smb + ((2 * GA16 + bk * 136 + bn0) << 2);
    const uint32_t aFrag = smb +
        (((wm + (lane & 15)) * 20 + ((lane >> 4) << 2)) << 2);

    float acc[4][4][4];
#pragma unroll
    for (int i = 0; i < 4; i++)
#pragma unroll
        for (int j = 0; j < 4; j++)
#pragma unroll
            for (int e = 0; e < 4; e++) acc[i][j][e] = 0.f;

    const int nk = K >> 5;

    auto issue = [&](int s) {
        const uint32_t so = (uint32_t)((s & 1) * GS_STG) << 2;
        const float* Ap = Ag + s * 32;
        CP16(aStg + so, Ap);
        CP16(aStg + so + 16, Ap + 4);
        CP16(aStg + so + (GA16 << 2), Ap + 16);
        CP16(aStg + so + (GA16 << 2) + 16, Ap + 20);
        const float* Bp = Bg + (size_t)s * 32 * N;
        CP16(bStg + so, Bp);
        CP16(bStg + so + 16, Bp + 4);
        const float* Bp1 = Bp + (size_t)16 * N;
        CP16(bStg + so + (GB16 << 2), Bp1);
        CP16(bStg + so + (GB16 << 2) + 16, Bp1 + 4);
    };

    issue(0); CP_COMMIT();

    for (int kt = 0; kt < nk; kt++) {
        CP_WAIT0();
        __syncthreads();
        if (kt + 1 < nk) { issue(kt + 1); CP_COMMIT(); }

        const uint32_t stg = (uint32_t)((kt & 1) * GS_STG);
        const uint32_t aS = aFrag + (stg << 2);
        const uint32_t* Bsl = sm + stg + 2 * GA16;

#pragma unroll
        for (int sb = 0; sb < 2; sb++) {
            const uint32_t aSb = aS + ((uint32_t)(sb * GA16) << 2);
            const uint32_t* Bs = Bsl + sb * GB16;
#pragma unroll
            for (int ks = 0; ks < 2; ks++) {
                const int k0 = ks * 8;
                uint32_t af[4][4], bf[4][2];
#pragma unroll
                for (int mt = 0; mt < 4; mt++)
                    ldmx4(af[mt], aSb + mt * 1280 + ks * 32);
#pragma unroll
                for (int nt = 0; nt < 4; nt++) {
                    const int n = wn + nt * 8 + g;
                    bf[nt][0] = Bs[(k0 + t) * 136 + n];
                    bf[nt][1] = Bs[(k0 + t + 4) * 136 + n];
                }
#pragma unroll
                for (int mt = 0; mt < 4; mt++)
#pragma unroll
                    for (int nt = 0; nt < 4; nt++)
                        mma8(acc[mt][nt], af[mt][0], af[mt][1], af[mt][2], af[mt][3],
                             bf[nt][0], bf[nt][1]);
            }
        }
    }

#pragma unroll
    for (int mt = 0; mt < 4; mt++) {
#pragma unroll
        for (int nt = 0; nt < 4; nt++) {
            const int r = bm + wm + mt * 16 + g;
            const int c = bn + wn + nt * 8 + 2 * t;
#pragma unroll
            for (int e = 0; e < 4; e++) {
                const int rr = r + ((e >> 1) << 3);
                const int cc = c + (e & 1);
                float v = acc[mt][nt][e];
                if (bias) v += bias[cc];
                v *= oscale;
                if (rnd) v = __uint_as_float(f2tf(v));
                int oc;
                if (mode == 0)      oc = cc;
                else if (mode == 1) oc = ((cc >> 7) << 8) + (cc & 127);
                else if (mode == 2) oc = ((cc >> 7) << 8) + permk(cc & 127);
                else {
                    int ww = cc & 127;
                    oc = (cc & ~127) + ((ww & 7) << 4) + (ww >> 3);
                }
                C[(size_t)rr * ldc + oc] = v;
            }
        }
    }
}

// ---------------- rope on q -> q_new[..., packed 128:256], scaled ----------
__global__ void rope_q_kernel(const float* __restrict__ in, float* __restrict__ qnew)
{
    int j = blockIdx.x * blockDim.x + threadIdx.x;
    int row = blockIdx.y;
    if (j >= 1024) return;
    int pos = row & (SEQ - 1);
    float inv = powf(10000.0f, -(float)j * (1.0f / 1024.0f));
    float ang = (float)pos * inv;
    float sn, cs;
    sincosf(ang, &sn, &cs);
    float x1 = in[(size_t)row * 2048 + j];
    float x2 = in[(size_t)row * 2048 + j + 1024];
    const float sc = 0.0625f;   // 1/sqrt(2*HEAD_DIM) = 2^-4, exact
    float o1 = __uint_as_float(f2tf((x1 * cs - x2 * sn) * sc));
    float o2 = __uint_as_float(f2tf((x2 * cs + x1 * sn) * sc));
    int c1 = j, c2 = j + 1024;
    qnew[(size_t)row * 4096 + (c1 >> 7) * 256 + permk(128 + (c1 & 127))] = o1;
    qnew[(size_t)row * 4096 + (c2 >> 7) * 256 + permk(128 + (c2 & 127))] = o2;
}

// ---------------- rope on k + broadcast to all heads (k-packed) ------------
__global__ void rope_k_kernel(const float* __restrict__ in, float* __restrict__ knew)
{
    int j = threadIdx.x;          // 0..63
    int row = blockIdx.x;
    int pos = row & (SEQ - 1);
    float inv = powf(10000.0f, -(float)j * (1.0f / 64.0f));
    float ang = (float)pos * inv;
    float sn, cs;
    sincosf(ang, &sn, &cs);
    float x1 = in[(size_t)row * 128 + j];
    float x2 = in[(size_t)row * 128 + j + 64];
    float o1 = __uint_as_float(f2tf(x1 * cs - x2 * sn));
    float o2 = __uint_as_float(f2tf(x2 * cs + x1 * sn));
    const int p1 = permk(128 + j);
    const int p2 = permk(128 + j + 64);
    float* base = knew + (size_t)row * 4096;
#pragma unroll
    for (int h = 0; h < NUM_HEADS; h++) {
        base[h * 256 + p1] = o1;
        base[h * 256 + p2] = o2;
    }
}

// ---------------- flash attention v6: barrier-free mainloop ----------------
// Bq=128 (8 warps x 16 rows), Bk=32. Q (packed, pre-scaled) staged once into
// smem [128][272]; Q-lo fragments hoisted to registers. K and V fragments
// loaded directly from gmem (LDG.128 through L1; packed layouts are already
// fragment-shaped). P is per-warp-private smem. NO __syncthreads and no
// cp.async waits inside the tile loop — warps run fully independently.
#define BQ   128
#define BK2  32
#define SQS2 272   // % 32 == 16 -> conflict-free LDS.128 Q frags
#define SPS  36
#define Q_WORDS2 (BQ * SQS2)         // 34816
#define P_WORDS2 (BQ * SPS)          // 4608
#define ATT_SMEM_BYTES ((Q_WORDS2 + P_WORDS2) * 4)   // 157696

__global__ void __launch_bounds__(256, 1) mla_attn_tf32(
    const float* __restrict__ Qn, const float* __restrict__ Kn,
    const float* __restrict__ Vp, float* __restrict__ Op)
{
    extern __shared__ uint32_t sw[];
    uint32_t* sQ = sw;                   // [128][272] packed Q (pre-scaled)
    uint32_t* sP = sQ + Q_WORDS2;        // [128][36]

    const int tid = threadIdx.x, lane = tid & 31, w = tid >> 5;
    const int g = lane >> 2, t = lane & 3;
    const int qt = (int)gridDim.x - 1 - (int)blockIdx.x;   // heavy CTAs first
    const int h = blockIdx.y, b = blockIdx.z;
    const int q0 = w * 16;

    // ---- stage Q (straight copy of packed rows) ----
    {
        const int r = tid >> 1, off = (tid & 1) * 128;
        const float* qp = Qn + (((size_t)(b * SEQ + qt * BQ + r)) * NUM_HEADS + h) * QK_DIM + off;
        uint32_t dst = sptr(sQ) + ((r * SQS2 + off) << 2);
#pragma unroll
        for (int j = 0; j < 32; j++) CP16(dst + j * 16, qp + j * 4);
        CP_COMMIT();
    }
    CP_WAIT0();
    __syncthreads();   // only barrier in the kernel

    // Q fragment base addresses (LDS.128, conflict-free at stride 272)
    const uint32_t qA0 = sptr(sQ) + (((q0 + g) * SQS2 + 4 * t) << 2);
    const uint32_t qB0 = qA0 + ((8 * SQS2) << 2);
    const uint32_t pAddr = sptr(sP) +
        (((q0 + (lane & 15)) * SPS + ((lane >> 4) << 2)) << 2);

    // hoist Q-lo fragments (dims 0..127) into registers
    uint4 qA[8], qB[8];
#pragma unroll
    for (int c = 0; c < 8; c++) {
        qA[c] = *(const uint4*)(sQ + ((qA0 - sptr(sQ)) >> 2) + c * 16);
        qB[c] = *(const uint4*)(sQ + ((qB0 - sptr(sQ)) >> 2) + c * 16);
    }

    // gmem lane bases for K and V fragments
    const float* kLane = Kn + (((size_t)(b * SEQ)) * NUM_HEADS + h) * QK_DIM
                         + (size_t)g * (NUM_HEADS * QK_DIM) + t * 4;
    const float* vLane = Vp + ((size_t)(b * SEQ)) * D_MODEL + h * HEAD_DIM
                         + (size_t)t * D_MODEL + g * 16;

    float oacc[16][4];
#pragma unroll
    for (int dt = 0; dt < 16; dt++)
#pragma unroll
        for (int e = 0; e < 4; e++) oacc[dt][e] = 0.f;
    float mA = -3e38f, mB = -3e38f, lA = 0.f, lB = 0.f;

    const int ntiles = 4 * qt + 4;

    for (int tt = 0; tt < ntiles; tt++) {
        const float* kT = kLane + (size_t)(tt * BK2) * (NUM_HEADS * QK_DIM);
        const float* vT = vLane + (size_t)(tt * BK2) * D_MODEL;

        // ---- S = Q @ K^T (16 q-rows x 32 keys per warp; K via LDG.128) ----
        float sacc[4][4];
#pragma unroll
        for (int j = 0; j < 4; j++)
#pragma unroll
            for (int e = 0; e < 4; e++) sacc[j][e] = 0.f;

        // dims 0..127 from registers
#pragma unroll
        for (int c = 0; c < 8; c++) {
#pragma unroll
            for (int j = 0; j < 4; j++) {
                const uint4 kf = *(const uint4*)(kT + (size_t)(j * 8) * (NUM_HEADS * QK_DIM) + c * 16);
                mma8(sacc[j], qA[c].x, qB[c].x, qA[c].y, qB[c].y, kf.x, kf.y);
                mma8(sacc[j], qA[c].z, qB[c].z, qA[c].w, qB[c].w, kf.z, kf.w);
            }
        }
        // dims 128..255 streamed from smem
#pragma unroll
        for (int c = 8; c < 16; c++) {
            const uint4 ua = *(const uint4*)(sQ + (q0 + g) * SQS2 + c * 16 + 4 * t);
            const uint4 ub = *(const uint4*)(sQ + (q0 + g + 8) * SQS2 + c * 16 + 4 * t);
#pragma unroll
            for (int j = 0; j < 4; j++) {
                const uint4 kf = *(const uint4*)(kT + (size_t)(j * 8) * (NUM_HEADS * QK_DIM) + c * 16);
                mma8(sacc[j], ua.x, ub.x, ua.y, ub.y, kf.x, kf.y);
                mma8(sacc[j], ua.z, ub.z, ua.w, ub.w, kf.z, kf.w);
            }
        }

        if (tt >= 4 * qt) {   // diagonal-region masking
            const int kb = tt * BK2 + 2 * t;
            const int qAr = qt * BQ + q0 + g, qBr = qAr + 8;
#pragma unroll
            for (int j = 0; j < 4; j++) {
                int k0g = kb + j * 8;
                if (k0g     > qAr) sacc[j][0] = -3e38f;
                if (k0g + 1 > qAr) sacc[j][1] = -3e38f;
                if (k0g     > qBr) sacc[j][2] = -3e38f;
                if (k0g + 1 > qBr) sacc[j][3] = -3e38f;
            }
        }

        // ---- online softmax (rows owned by quads) ----
        float rmA = -3e38f, rmB = -3e38f;
#pragma unroll
        for (int j = 0; j < 4; j++) {
            rmA = fmaxf(rmA, fmaxf(sacc[j][0], sacc[j][1]));
            rmB = fmaxf(rmB, fmaxf(sacc[j][2], sacc[j][3]));
        }
        rmA = fmaxf(rmA, __shfl_xor_sync(0xffffffffu, rmA, 1));
        rmA = fmaxf(rmA, __shfl_xor_sync(0xffffffffu, rmA, 2));
        rmB = fmaxf(rmB, __shfl_xor_sync(0xffffffffu, rmB, 1));
        rmB = fmaxf(rmB, __shfl_xor_sync(0xffffffffu, rmB, 2));
        float mnA = fmaxf(mA, rmA), mnB = fmaxf(mB, rmB);
        float aAl = fast_exp(mA - mnA), aBl = fast_exp(mB - mnB);
        mA = mnA; mB = mnB;

        float lsA = 0.f, lsB = 0.f;
        uint32_t* pA = sP + (q0 + g) * SPS;
        uint32_t* pB = pA + 8 * SPS;
#pragma unroll
        for (int j = 0; j < 4; j++) {
            uint32_t p0 = f2tf(fast_exp(sacc[j][0] - mnA));
            uint32_t p1 = f2tf(fast_exp(sacc[j][1] - mnA));
            uint32_t p2 = f2tf(fast_exp(sacc[j][2] - mnB));
            uint32_t p3 = f2tf(fast_exp(sacc[j][3] - mnB));
            lsA += __uint_as_float(p0) + __uint_as_float(p1);
            lsB += __uint_as_float(p2) + __uint_as_float(p3);
            pA[j * 8 + 2 * t] = p0; pA[j * 8 + 2 * t + 1] = p1;
            pB[j * 8 + 2 * t] = p2; pB[j * 8 + 2 * t + 1] = p3;
        }
        lsA += __shfl_xor_sync(0xffffffffu, lsA, 1);
        lsA += __shfl_xor_sync(0xffffffffu, lsA, 2);
        lsB += __shfl_xor_sync(0xffffffffu, lsB, 1);
        lsB += __shfl_xor_sync(0xffffffffu, lsB, 2);
        lA = lA * aAl + lsA;
        lB = lB * aBl + lsB;

#pragma unroll
        for (int dt = 0; dt < 16; dt++) {
            oacc[dt][0] *= aAl; oacc[dt][1] *= aAl;
            oacc[dt][2] *= aBl; oacc[dt][3] *= aBl;
        }
        __syncwarp();

        // ---- O += P @ V (V via LDG.128; packed = 4 consecutive dt operands)
#pragma unroll
        for (int k0 = 0; k0 < BK2; k0 += 8) {
            uint32_t p[4];
            ldmx4(p, pAddr + k0 * 4);
            const float* vr0 = vT + (size_t)k0 * D_MODEL;
            const float* vr1 = vr0 + (size_t)4 * D_MODEL;
#pragma unroll
            for (int u = 0; u < 4; u++) {
                const uint4 v0 = *(const uint4*)(vr0 + u * 4);
                const uint4 v1 = *(const uint4*)(vr1 + u * 4);
                mma8(oacc[u * 4 + 0], p[0], p[1], p[2], p[3], v0.x, v1.x);
                mma8(oacc[u * 4 + 1], p[0], p[1], p[2], p[3], v0.y, v1.y);
                mma8(oacc[u * 4 + 2], p[0], p[1], p[2], p[3], v0.z, v1.z);
                mma8(oacc[u * 4 + 3], p[0], p[1], p[2], p[3], v0.w, v1.w);
            }
        }
        __syncwarp();
    }

    // normalize + write (tf32-rounded: feeds final cp.async GEMM)
    float iA = 1.f / lA, iB = 1.f / lB;
    float* oA = Op + ((size_t)(b * SEQ + qt * BQ + q0 + g)) * D_MODEL + h * HEAD_DIM;
    float* oB = oA + (size_t)8 * D_MODEL;
#pragma unroll
    for (int dt = 0; dt < 16; dt++) {
        int c = dt * 8 + 2 * t;
        *(uint2*)(oA + c) = make_uint2(f2tf(oacc[dt][0] * iA), f2tf(oacc[dt][1] * iA));
        *(uint2*)(oB + c) = make_uint2(f2tf(oacc[dt][2] * iB), f2tf(oacc[dt][3] * iB));
    }
}

// ---------------------------------------------------------------------------
extern "C" void kernel_launch(void* const* d_in, const int* in_sizes, int n_in,
                              void* d_out, int out_size)
{
    const float* inq  = (const float*)d_in[0];
    const float* ink  = (const float*)d_in[1];
    const float* Wqd  = (const float*)d_in[3];
    const float* Wkvd = (const float*)d_in[4];
    const float* Wqu  = (const float*)d_in[5];
    const float* Wku  = (const float*)d_in[6];
    const float* Wvu  = (const float*)d_in[7];
    const float* Wqr  = (const float*)d_in[8];
    const float* Wkr  = (const float*)d_in[9];
    const float* Wo   = (const float*)d_in[10];
    const float* bo   = (const float*)d_in[11];
    float* out = (float*)d_out;

    float *qlat, *kvlat, *qnew, *knew, *vbuf, *attn, *qrt, *krt;
    float *rinq, *rink, *rWqd, *rWkvd, *rWqu, *rWqr, *rWku, *rWvu, *rWkr, *rWo;
    cudaGetSymbolAddress((void**)&qlat,  g_qlat);
    cudaGetSymbolAddress((void**)&kvlat, g_kvlat);
    cudaGetSymbolAddress((void**)&qnew,  g_qnew);
    cudaGetSymbolAddress((void**)&knew,  g_knew);
    cudaGetSymbolAddress((void**)&vbuf,  g_v);
    cudaGetSymbolAddress((void**)&attn,  g_attn);
    cudaGetSymbolAddress((void**)&qrt,   g_qrt);
    cudaGetSymbolAddress((void**)&krt,   g_krt);
    cudaGetSymbolAddress((void**)&rinq,  g_rinq);
    cudaGetSymbolAddress((void**)&rink,  g_rink);
    cudaGetSymbolAddress((void**)&rWqd,  g_rWqd);
    cudaGetSymbolAddress((void**)&rWkvd, g_rWkvd);
    cudaGetSymbolAddress((void**)&rWqu,  g_rWqu);
    cudaGetSymbolAddress((void**)&rWqr,  g_rWqr);
    cudaGetSymbolAddress((void**)&rWku,  g_rWku);
    cudaGetSymbolAddress((void**)&rWvu,  g_rWvu);
    cudaGetSymbolAddress((void**)&rWkr,  g_rWkr);
    cudaGetSymbolAddress((void**)&rWo,   g_rWo);

    cudaFuncSetAttribute(tf32gemm,
                         cudaFuncAttributeMaxDynamicSharedMemorySize, GEMM_SMEM_BYTES);
    cudaFuncSetAttribute(mla_attn_tf32,
                         cudaFuncAttributeMaxDynamicSharedMemorySize, ATT_SMEM_BYTES);

    // 0) pre-round inputs + weights to tf32 (one pass)
    roundmany<<<RPT / 256, 256>>>(
        inq, rinq, ink, rink, Wqd, rWqd, Wkvd, rWkvd, Wqu, rWqu,
        Wqr, rWqr, Wku, rWku, Wvu, rWvu, Wkr, rWkr, Wo, rWo);

    // 1) q_latent = inputs_q @ Wq_down
    tf32gemm<<<dim3(Q_LATD / 128, ROWS / 128), 256, GEMM_SMEM_BYTES>>>(
        rinq, rWqd, qlat, nullptr, ROWS, Q_LATD, D_MODEL, Q_LATD, 0, 1, 1.0f);
    // 2) kv_latent = inputs_k @ Wkv_down
    tf32gemm<<<dim3(KV_LATD / 128, ROWS / 128), 256, GEMM_SMEM_BYTES>>>(
        rink, rWkvd, kvlat, nullptr, ROWS, KV_LATD, D_MODEL, KV_LATD, 0, 1, 1.0f);
    // 3) q_proj -> q_new[..., 0:128] (interleave + kpack, pre-scaled 2^-4)
    tf32gemm<<<dim3(D_MODEL / 128, ROWS / 128), 256, GEMM_SMEM_BYTES>>>(
        qlat, rWqu, qnew, nullptr, ROWS, D_MODEL, Q_LATD, 4096, 2, 1, 0.0625f);
    // 4) q_rope pre-projection
    tf32gemm<<<dim3(D_MODEL / 128, ROWS / 128), 256, GEMM_SMEM_BYTES>>>(
        qlat, rWqr, qrt, nullptr, ROWS, D_MODEL, Q_LATD, D_MODEL, 0, 1, 1.0f);
    // 5) rope(q) -> q_new[..., packed 128:256] (pre-scaled 2^-4)
    rope_q_kernel<<<dim3(4, ROWS), 256>>>(qrt, qnew);
    // 6) k_proj -> k_new[..., 0:128] (interleave + kpack)
    tf32gemm<<<dim3(D_MODEL / 128, ROWS / 128), 256, GEMM_SMEM_BYTES>>>(
        kvlat, rWku, knew, nullptr, ROWS, D_MODEL, KV_LATD, 4096, 2, 1, 1.0f);
    // 7) v_proj (vpack)
    tf32gemm<<<dim3(D_MODEL / 128, ROWS / 128), 256, GEMM_SMEM_BYTES>>>(
        kvlat, rWvu, vbuf, nullptr, ROWS, D_MODEL, KV_LATD, D_MODEL, 3, 1, 1.0f);
    // 8) k_rope pre-projection
    tf32gemm<<<dim3(HEAD_DIM / 128, ROWS / 128), 256, GEMM_SMEM_BYTES>>>(
        rink, rWkr, krt, nullptr, ROWS, HEAD_DIM, D_MODEL, HEAD_DIM, 0, 1, 1.0f);
    // 9) rope(k) + broadcast (kpack) -> k_new[..., 128:256]
    rope_k_kernel<<<ROWS, 64>>>(krt, knew);

    // 10) causal flash attention (barrier-free, K/V via L1)
    mla_attn_tf32<<<dim3(SEQ / BQ, NUM_HEADS, BATCH), 256, ATT_SMEM_BYTES>>>(
        qnew, knew, vbuf, attn);

    // 11) final projection + bias (full precision out)
    tf32gemm<<<dim3(D_MODEL / 128, ROWS / 128), 256, GEMM_SMEM_BYTES>>>(
        attn, rWo, out, bo, ROWS, D_MODEL, D_MODEL, D_MODEL, 0, 0, 1.0f);
}

// round 13
// speedup vs baseline: 1.1530x; 1.1530x over previous
#include <cuda_runtime.h>
#include <math.h>
#include <stdint.h>

#define D_MODEL   2048
#define Q_LATD    1536
#define KV_LATD   512
#define NUM_HEADS 16
#define HEAD_DIM  128
#define BATCH     2
#define SEQ       2048
#define ROWS      (BATCH * SEQ)      // 4096
#define QK_DIM    256                // head_dim(128) + rope(128)

// ---------------- scratch (device globals; no allocation allowed) ----------
__device__ float g_qlat[ROWS * Q_LATD];
__device__ float g_kvlat[ROWS * KV_LATD];
__device__ float g_qnew[(size_t)ROWS * NUM_HEADS * QK_DIM];   // [b,s,h,256] natural
__device__ float g_knew[(size_t)ROWS * NUM_HEADS * QK_DIM];   // [b,s,h,256] k-packed
__device__ float g_v[(size_t)ROWS * D_MODEL];                 // [b,s,h*128] v-packed
__device__ float g_attn[(size_t)ROWS * D_MODEL];
__device__ float g_qrt[(size_t)ROWS * D_MODEL];
__device__ float g_krt[(size_t)ROWS * HEAD_DIM];
// pre-rounded inputs + weights (tf32 bit patterns)
__device__ float g_rinq[(size_t)ROWS * D_MODEL];
__device__ float g_rink[(size_t)ROWS * D_MODEL];
__device__ float g_rWqd[(size_t)D_MODEL * Q_LATD];
__device__ float g_rWkvd[(size_t)D_MODEL * KV_LATD];
__device__ float g_rWqu[(size_t)Q_LATD * D_MODEL];
__device__ float g_rWqr[(size_t)Q_LATD * D_MODEL];
__device__ float g_rWku[(size_t)KV_LATD * D_MODEL];
__device__ float g_rWvu[(size_t)KV_LATD * D_MODEL];
__device__ float g_rWkr[(size_t)D_MODEL * HEAD_DIM];
__device__ float g_rWo[(size_t)D_MODEL * D_MODEL];

// ---------------- helpers --------------------------------------------------
__device__ __forceinline__ uint32_t f2tf(float x) {
    uint32_t u;
    asm("cvt.rna.tf32.f32 %0, %1;" : "=r"(u) : "f"(x));
    return u;
}

__device__ __forceinline__ uint32_t sptr(const void* p) {
    return (uint32_t)__cvta_generic_to_shared(p);
}

__device__ __forceinline__ void mma8(float c[4],
    uint32_t a0, uint32_t a1, uint32_t a2, uint32_t a3,
    uint32_t b0, uint32_t b1)
{
    asm volatile(
        "mma.sync.aligned.m16n8k8.row.col.f32.tf32.tf32.f32 "
        "{%0,%1,%2,%3}, {%4,%5,%6,%7}, {%8,%9}, {%0,%1,%2,%3};\n"
        : "+f"(c[0]), "+f"(c[1]), "+f"(c[2]), "+f"(c[3])
        : "r"(a0), "r"(a1), "r"(a2), "r"(a3), "r"(b0), "r"(b1));
}

__device__ __forceinline__ void ldmx4(uint32_t a[4], uint32_t addr) {
    asm volatile(
        "ldmatrix.sync.aligned.m8n8.x4.shared.b16 {%0,%1,%2,%3}, [%4];"
        : "=r"(a[0]), "=r"(a[1]), "=r"(a[2]), "=r"(a[3]) : "r"(addr));
}

#define CP16(dst, src) \
    asm volatile("cp.async.cg.shared.global [%0], [%1], 16;" :: "r"(dst), "l"(src))
#define CP_COMMIT() asm volatile("cp.async.commit_group;" ::: "memory")
#define CP_WAIT0()  asm volatile("cp.async.wait_group 0;" ::: "memory")

// exp(x) for x <= 0 on the FMA pipe only (no MUFU)
__device__ __forceinline__ float fast_exp(float x) {
    float y  = fmaxf(x * 1.4426950408889634f, -126.0f);
    float tb = y + 12582912.0f;
    float nf = tb - 12582912.0f;
    float u  = (y - nf) * 0.6931471805599453f;
    float p  = fmaf(u, 0.008333334f, 0.041666668f);
    p = fmaf(p, u, 0.16666667f);
    p = fmaf(p, u, 0.5f);
    p = fmaf(p, u, 1.0f);
    p = fmaf(p, u, 1.0f);
    return p * __int_as_float(((int)nf + 127) << 23);
}

// digit-swap within a 16-chunk: stored pos 4t+j holds original t+4j
__device__ __forceinline__ int permk(int k) {
    return (k & ~15) | (((k & 3) << 2) | ((k >> 2) & 3));
}

// ---------------- fused pre-round pass (float4 granularity) ----------------
#define RP1 2097152u
#define RP2 4194304u
#define RP3 4980736u
#define RP4 5242880u
#define RP5 6029312u
#define RP6 6815744u
#define RP7 7077888u
#define RP8 7340032u
#define RP9 7405568u
#define RPT 8454144u

__global__ void roundmany(
    const float* s0, float* d0, const float* s1, float* d1,
    const float* s2, float* d2, const float* s3, float* d3,
    const float* s4, float* d4, const float* s5, float* d5,
    const float* s6, float* d6, const float* s7, float* d7,
    const float* s8, float* d8, const float* s9, float* d9)
{
    uint32_t i = blockIdx.x * 256u + threadIdx.x;
    const float* s; float* d; uint32_t off;
    if      (i < RP1) { s = s0; d = d0; off = i; }
    else if (i < RP2) { s = s1; d = d1; off = i - RP1; }
    else if (i < RP3) { s = s2; d = d2; off = i - RP2; }
    else if (i < RP4) { s = s3; d = d3; off = i - RP3; }
    else if (i < RP5) { s = s4; d = d4; off = i - RP4; }
    else if (i < RP6) { s = s5; d = d5; off = i - RP5; }
    else if (i < RP7) { s = s6; d = d6; off = i - RP6; }
    else if (i < RP8) { s = s7; d = d7; off = i - RP7; }
    else if (i < RP9) { s = s8; d = d8; off = i - RP8; }
    else              { s = s9; d = d9; off = i - RP9; }
    float4 v = ((const float4*)s)[off];
    ((uint4*)d)[off] = make_uint4(f2tf(v.x), f2tf(v.y), f2tf(v.z), f2tf(v.w));
}

// ---------------- tf32 GEMM v5 (round-9/10 verbatim) -----------------------
#define GA16 2560
#define GB16 2176
#define GS_STG (2 * GA16 + 2 * GB16)        // 9472 words per 32-k stage
#define GEMM_SMEM_BYTES (2 * GS_STG * 4)    // 75776 B

__global__ void __launch_bounds__(256, 2) tf32gemm(
    const float* __restrict__ A, const float* __restrict__ B,
    float* __restrict__ C, const float* __restrict__ bias,
    int M, int N, int K, int ldc, int mode, int rnd)
{
    extern __shared__ uint32_t sm[];
    const int tid = threadIdx.x, lane = tid & 31, w = tid >> 5;
    const int g = lane >> 2, t = lane & 3;
    const int wm = (w & 1) * 64, wn = (w >> 1) * 32;
    const int bm = blockIdx.y * 128, bn = blockIdx.x * 128;

    const int am = tid >> 1, ak = (tid & 1) * 8;
    const int bk = tid >> 4, bn0 = (tid & 15) * 8;
    const float* Ag = A + (size_t)(bm + am) * K + ak;
    const float* Bg = B + (size_t)bk * N + bn + bn0;

    const uint32_t smb = sptr(sm);
    const uint32_t aStg = smb + ((am * 20 + ak) << 2);
    const uint32_t bStg = smb + ((2 * GA16 + bk * 136 + bn0) << 2);
    const uint32_t aFrag = smb +
        (((wm + (lane & 15)) * 20 + ((lane >> 4) << 2)) << 2);

    float acc[4][4][4];
#pragma unroll
    for (int i = 0; i < 4; i++)
#pragma unroll
        for (int j = 0; j < 4; j++)
#pragma unroll
            for (int e = 0; e < 4; e++) acc[i][j][e] = 0.f;

    const int nk = K >> 5;

    auto issue = [&](int s) {
        const uint32_t so = (uint32_t)((s & 1) * GS_STG) << 2;
        const float* Ap = Ag + s * 32;
        CP16(aStg + so, Ap);
        CP16(aStg + so + 16, Ap + 4);
        CP16(aStg + so + (GA16 << 2), Ap + 16);
        CP16(aStg + so + (GA16 << 2) + 16, Ap + 20);
        const float* Bp = Bg + (size_t)s * 32 * N;
        CP16(bStg + so, Bp);
        CP16(bStg + so + 16, Bp + 4);
        const float* Bp1 = Bp + (size_t)16 * N;
        CP16(bStg + so + (GB16 << 2), Bp1);
        CP16(bStg + so + (GB16 << 2) + 16, Bp1 + 4);
    };

    issue(0); CP_COMMIT();

    for (int kt = 0; kt < nk; kt++) {
        CP_WAIT0();
        __syncthreads();
        if (kt + 1 < nk) { issue(kt + 1); CP_COMMIT(); }

        const uint32_t stg = (uint32_t)((kt & 1) * GS_STG);
        const uint32_t aS = aFrag + (stg << 2);
        const uint32_t* Bsl = sm + stg + 2 * GA16;

#pragma unroll
        for (int sb = 0; sb < 2; sb++) {
            const uint32_t aSb = aS + ((uint32_t)(sb * GA16) << 2);
            const uint32_t* Bs = Bsl + sb * GB16;
#pragma unroll
            for (int ks = 0; ks < 2; ks++) {
                const int k0 = ks * 8;
                uint32_t af[4][4], bf[4][2];
#pragma unroll
                for (int mt = 0; mt < 4; mt++)
                    ldmx4(af[mt], aSb + mt * 1280 + ks * 32);
#pragma unroll
                for (int nt = 0; nt < 4; nt++) {
                    const int n = wn + nt * 8 + g;
                    bf[nt][0] = Bs[(k0 + t) * 136 + n];
                    bf[nt][1] = Bs[(k0 + t + 4) * 136 + n];
                }
#pragma unroll
                for (int mt = 0; mt < 4; mt++)
#pragma unroll
                    for (int nt = 0; nt < 4; nt++)
                        mma8(acc[mt][nt], af[mt][0], af[mt][1], af[mt][2], af[mt][3],
                             bf[nt][0], bf[nt][1]);
            }
        }
    }

#pragma unroll
    for (int mt = 0; mt < 4; mt++) {
#pragma unroll
        for (int nt = 0; nt < 4; nt++) {
            const int r = bm + wm + mt * 16 + g;
            const int c = bn + wn + nt * 8 + 2 * t;
#pragma unroll
            for (int e = 0; e < 4; e++) {
                const int rr = r + ((e >> 1) << 3);
                const int cc = c + (e & 1);
                float v = acc[mt][nt][e];
                if (bias) v += bias[cc];
                if (rnd) v = __uint_as_float(f2tf(v));
                int oc;
                if (mode == 0)      oc = cc;
                else if (mode == 1) oc = ((cc >> 7) << 8) + (cc & 127);
                else if (mode == 2) oc = ((cc >> 7) << 8) + permk(cc & 127);
                else {
                    int ww = cc & 127;
                    oc = (cc & ~127) + ((ww & 7) << 4) + (ww >> 3);
                }
                C[(size_t)rr * ldc + oc] = v;
            }
        }
    }
}

// ---------------- rope on q (full 2048 dims) -> q_new[...,128:256] ---------
__global__ void rope_q_kernel(const float* __restrict__ in, float* __restrict__ qnew)
{
    int j = blockIdx.x * blockDim.x + threadIdx.x;
    int row = blockIdx.y;
    if (j >= 1024) return;
    int pos = row & (SEQ - 1);
    float inv = powf(10000.0f, -(float)j * (1.0f / 1024.0f));
    float ang = (float)pos * inv;
    float sn, cs;
    sincosf(ang, &sn, &cs);
    float x1 = in[(size_t)row * 2048 + j];
    float x2 = in[(size_t)row * 2048 + j + 1024];
    float o1 = __uint_as_float(f2tf(x1 * cs - x2 * sn));
    float o2 = __uint_as_float(f2tf(x2 * cs + x1 * sn));
    int c1 = j, c2 = j + 1024;
    qnew[(size_t)row * 4096 + (c1 >> 7) * 256 + (c1 & 127) + 128] = o1;
    qnew[(size_t)row * 4096 + (c2 >> 7) * 256 + (c2 & 127) + 128] = o2;
}

// ---------------- rope on k + broadcast to all heads (k-packed) ------------
__global__ void rope_k_kernel(const float* __restrict__ in, float* __restrict__ knew)
{
    int j = threadIdx.x;          // 0..63
    int row = blockIdx.x;
    int pos = row & (SEQ - 1);
    float inv = powf(10000.0f, -(float)j * (1.0f / 64.0f));
    float ang = (float)pos * inv;
    float sn, cs;
    sincosf(ang, &sn, &cs);
    float x1 = in[(size_t)row * 128 + j];
    float x2 = in[(size_t)row * 128 + j + 64];
    float o1 = __uint_as_float(f2tf(x1 * cs - x2 * sn));
    float o2 = __uint_as_float(f2tf(x2 * cs + x1 * sn));
    const int p1 = permk(128 + j);
    const int p2 = permk(128 + j + 64);
    float* base = knew + (size_t)row * 4096;
#pragma unroll
    for (int h = 0; h < NUM_HEADS; h++) {
        base[h * 256 + p1] = o1;
        base[h * 256 + p2] = o2;
    }
}

// ---------------- flash attention v5 (round-10 verbatim) -------------------
#define BQ   128
#define BK2  32
#define SQH  132   // % 32 == 4  -> conflict-free ldmatrix rows
#define SKS  272   // % 32 == 16 -> conflict-free LDS.128 K frags
#define SVS  132   // % 32 == 4  -> conflict-free LDS.128 V frags
#define SPS  36
#define QH_WORDS (BQ * SQH)          // 16896
#define K_WORDS  (2 * BK2 * SKS)     // 17408 (>= QH_WORDS: doubles as Q-lo scratch)
#define V_WORDS  (2 * BK2 * SVS)     // 8448
#define P_WORDS  (BQ * SPS)          // 4608
#define ATT_SMEM_BYTES ((QH_WORDS + K_WORDS + V_WORDS + P_WORDS) * 4)  // 189440

__global__ void __launch_bounds__(256, 1) mla_attn_tf32(
    const float* __restrict__ Qn, const float* __restrict__ Kn,
    const float* __restrict__ Vp, float* __restrict__ Op)
{
    extern __shared__ uint32_t sw[];
    uint32_t* sQh = sw;                  // [128][132] Q dims 128..255
    uint32_t* sK  = sQh + QH_WORDS;      // [2][32][272] (scratch for Q-lo at init)
    uint32_t* sV  = sK + K_WORDS;        // [2][32][132]
    uint32_t* sP  = sV + V_WORDS;        // [128][36]

    const int tid = threadIdx.x, lane = tid & 31, w = tid >> 5;
    const int g = lane >> 2, t = lane & 3;
    const int qt = blockIdx.x, h = blockIdx.y, b = blockIdx.z;
    const int q0 = w * 16;

    const uint32_t qhAddr = sptr(sQh) +
        (((q0 + (lane & 15)) * SQH + ((lane >> 4) << 2)) << 2);
    const uint32_t qloAddr = sptr(sK) +
        (((q0 + (lane & 15)) * SQH + ((lane >> 4) << 2)) << 2);
    const uint32_t pAddr = sptr(sP) +
        (((q0 + (lane & 15)) * SPS + ((lane >> 4) << 2)) << 2);
    const uint32_t kBase = sptr(sK), vBase = sptr(sV);

    // ---- stage Q: lo half into K-region scratch, hi half into sQh ----
    {
        const int r = tid >> 1, d0 = (tid & 1) * 64;
        const float* qp = Qn + (((size_t)(b * SEQ + qt * BQ + r)) * NUM_HEADS + h) * QK_DIM;
        const float sc = 0.0625f;   // 1/sqrt(2*HEAD_DIM) = 2^-4 exact
        uint32_t* dlo = (uint32_t*)sK + r * SQH + d0;
        uint32_t* dhi = sQh + r * SQH + d0;
#pragma unroll
        for (int j = 0; j < 16; j++) {
            float4 v = *(const float4*)(qp + d0 + j * 4);
            *(uint4*)(dlo + j * 4) = make_uint4(
                __float_as_uint(v.x * sc), __float_as_uint(v.y * sc),
                __float_as_uint(v.z * sc), __float_as_uint(v.w * sc));
            float4 u = *(const float4*)(qp + 128 + d0 + j * 4);
            *(uint4*)(dhi + j * 4) = make_uint4(
                __float_as_uint(u.x * sc), __float_as_uint(u.y * sc),
                __float_as_uint(u.z * sc), __float_as_uint(u.w * sc));
        }
    }
    __syncthreads();

    // hoist Q-lo fragments (dims 0..127) into registers
    uint32_t qreg[16][4];
#pragma unroll
    for (int c = 0; c < 8; c++) {
        ldmx4(qreg[2 * c],     qloAddr + c * 64);
        ldmx4(qreg[2 * c + 1], qloAddr + c * 64 + 32);
    }
    __syncthreads();   // all warps done reading scratch before K prefetch

    const int sr  = tid >> 3;          // staging row 0..31
    const int ks8 = (tid & 7) * 32;    // K seg: 32 words
    const int vs8 = (tid & 7) * 16;    // V seg: 16 words

    const int ntiles = 4 * qt + 4;

    auto prefetchKV = [&](int tile) {
        const int slot = tile & 1;
        const float* kp = Kn + (((size_t)(b * SEQ + tile * BK2 + sr)) * NUM_HEADS + h) * QK_DIM + ks8;
        uint32_t kd = kBase + ((slot * BK2 * SKS + sr * SKS + ks8) << 2);
#pragma unroll
        for (int j = 0; j < 8; j++) CP16(kd + j * 16, kp + j * 4);
        const float* vp = Vp + ((size_t)(b * SEQ + tile * BK2 + sr)) * D_MODEL + h * HEAD_DIM + vs8;
        uint32_t vd = vBase + ((slot * BK2 * SVS + sr * SVS + vs8) << 2);
#pragma unroll
        for (int j = 0; j < 4; j++) CP16(vd + j * 16, vp + j * 4);
    };

    prefetchKV(0); CP_COMMIT();

    float oacc[16][4];
#pragma unroll
    for (int dt = 0; dt < 16; dt++)
#pragma unroll
        for (int e = 0; e < 4; e++) oacc[dt][e] = 0.f;
    float mA = -3e38f, mB = -3e38f, lA = 0.f, lB = 0.f;

    for (int tt = 0; tt < ntiles; tt++) {
        CP_WAIT0();
        __syncthreads();
        if (tt + 1 < ntiles) { prefetchKV(tt + 1); CP_COMMIT(); }

        const uint32_t* sKb = sK + (tt & 1) * BK2 * SKS;
        const uint32_t* sVb = sV + (tt & 1) * BK2 * SVS;

        // S = Q @ K^T  (16 q-rows x 32 keys per warp)
        float sacc[4][4];
#pragma unroll
        for (int j = 0; j < 4; j++)
#pragma unroll
            for (int e = 0; e < 4; e++) sacc[j][e] = 0.f;

        // dims 0..127 from registers
#pragma unroll
        for (int c = 0; c < 8; c++) {
#pragma unroll
            for (int j = 0; j < 4; j++) {
                const uint4 kf = *(const uint4*)&sKb[(j * 8 + g) * SKS + c * 16 + t * 4];
                mma8(sacc[j], qreg[2*c][0], qreg[2*c][1], qreg[2*c][2], qreg[2*c][3],
                     kf.x, kf.y);
                mma8(sacc[j], qreg[2*c+1][0], qreg[2*c+1][1], qreg[2*c+1][2], qreg[2*c+1][3],
                     kf.z, kf.w);
            }
        }
        // dims 128..255 streamed from compact sQh
#pragma unroll
        for (int c = 0; c < 8; c++) {
            uint32_t a0[4], a1[4];
            ldmx4(a0, qhAddr + c * 64);
            ldmx4(a1, qhAddr + c * 64 + 32);
#pragma unroll
            for (int j = 0; j < 4; j++) {
                const uint4 kf = *(const uint4*)&sKb[(j * 8 + g) * SKS + (c + 8) * 16 + t * 4];
                mma8(sacc[j], a0[0], a0[1], a0[2], a0[3], kf.x, kf.y);
                mma8(sacc[j], a1[0], a1[1], a1[2], a1[3], kf.z, kf.w);
            }
        }

        if (tt >= 4 * qt) {   // diagonal-region masking
            const int kb = tt * BK2 + 2 * t;
            const int qA = qt * BQ + q0 + g, qB = qA + 8;
#pragma unroll
            for (int j = 0; j < 4; j++) {
                int k0g = kb + j * 8;
                if (k0g     > qA) sacc[j][0] = -3e38f;
                if (k0g + 1 > qA) sacc[j][1] = -3e38f;
                if (k0g     > qB) sacc[j][2] = -3e38f;
                if (k0g + 1 > qB) sacc[j][3] = -3e38f;
            }
        }

        // online softmax (rows owned by quads)
        float rmA = -3e38f, rmB = -3e38f;
#pragma unroll
        for (int j = 0; j < 4; j++) {
            rmA = fmaxf(rmA, fmaxf(sacc[j][0], sacc[j][1]));
            rmB = fmaxf(rmB, fmaxf(sacc[j][2], sacc[j][3]));
        }
        rmA = fmaxf(rmA, __shfl_xor_sync(0xffffffffu, rmA, 1));
        rmA = fmaxf(rmA, __shfl_xor_sync(0xffffffffu, rmA, 2));
        rmB = fmaxf(rmB, __shfl_xor_sync(0xffffffffu, rmB, 1));
        rmB = fmaxf(rmB, __shfl_xor_sync(0xffffffffu, rmB, 2));
        float mnA = fmaxf(mA, rmA), mnB = fmaxf(mB, rmB);
        float aAl = fast_exp(mA - mnA), aBl = fast_exp(mB - mnB);
        mA = mnA; mB = mnB;

        float lsA = 0.f, lsB = 0.f;
        uint32_t* pA = sP + (q0 + g) * SPS;
        uint32_t* pB = pA + 8 * SPS;
#pragma unroll
        for (int j = 0; j < 4; j++) {
            uint32_t p0 = f2tf(fast_exp(sacc[j][0] - mnA));
            uint32_t p1 = f2tf(fast_exp(sacc[j][1] - mnA));
            uint32_t p2 = f2tf(fast_exp(sacc[j][2] - mnB));
            uint32_t p3 = f2tf(fast_exp(sacc[j][3] - mnB));
            lsA += __uint_as_float(p0) + __uint_as_float(p1);
            lsB += __uint_as_float(p2) + __uint_as_float(p3);
            pA[j * 8 + 2 * t] = p0; pA[j * 8 + 2 * t + 1] = p1;
            pB[j * 8 + 2 * t] = p2; pB[j * 8 + 2 * t + 1] = p3;
        }
        lsA += __shfl_xor_sync(0xffffffffu, lsA, 1);
        lsA += __shfl_xor_sync(0xffffffffu, lsA, 2);
        lsB += __shfl_xor_sync(0xffffffffu, lsB, 1);
        lsB += __shfl_xor_sync(0xffffffffu, lsB, 2);
        lA = lA * aAl + lsA;
        lB = lB * aBl + lsB;

#pragma unroll
        for (int dt = 0; dt < 16; dt++) {
            oacc[dt][0] *= aAl; oacc[dt][1] *= aAl;
            oacc[dt][2] *= aBl; oacc[dt][3] *= aBl;
        }
        __syncwarp();

        // O += P @ V  (V packed: one LDS.128 = 4 consecutive dt operands)
#pragma unroll
        for (int k0 = 0; k0 < BK2; k0 += 8) {
            uint32_t p[4];
            ldmx4(p, pAddr + k0 * 4);
            const uint32_t* vr0 = sVb + (k0 + t) * SVS + g * 16;
            const uint32_t* vr1 = sVb + (k0 + t + 4) * SVS + g * 16;
#pragma unroll
            for (int u = 0; u < 4; u++) {
                const uint4 v0 = *(const uint4*)&vr0[u * 4];
                const uint4 v1 = *(const uint4*)&vr1[u * 4];
                mma8(oacc[u * 4 + 0], p[0], p[1], p[2], p[3], v0.x, v1.x);
                mma8(oacc[u * 4 + 1], p[0], p[1], p[2], p[3], v0.y, v1.y);
                mma8(oacc[u * 4 + 2], p[0], p[1], p[2], p[3], v0.z, v1.z);
                mma8(oacc[u * 4 + 3], p[0], p[1], p[2], p[3], v0.w, v1.w);
            }
        }
    }

    // normalize + write (tf32-rounded: feeds final cp.async GEMM)
    float iA = 1.f / lA, iB = 1.f / lB;
    float* oA = Op + ((size_t)(b * SEQ + qt * BQ + q0 + g)) * D_MODEL + h * HEAD_DIM;
    float* oB = oA + (size_t)8 * D_MODEL;
#pragma unroll
    for (int dt = 0; dt < 16; dt++) {
        int c = dt * 8 + 2 * t;
        *(uint2*)(oA + c) = make_uint2(f2tf(oacc[dt][0] * iA), f2tf(oacc[dt][1] * iA));
        *(uint2*)(oB + c) = make_uint2(f2tf(oacc[dt][2] * iB), f2tf(oacc[dt][3] * iB));
    }
}

// ---------------------------------------------------------------------------
extern "C" void kernel_launch(void* const* d_in, const int* in_sizes, int n_in,
                              void* d_out, int out_size)
{
    const float* inq  = (const float*)d_in[0];
    const float* ink  = (const float*)d_in[1];
    const float* Wqd  = (const float*)d_in[3];
    const float* Wkvd = (const float*)d_in[4];
    const float* Wqu  = (const float*)d_in[5];
    const float* Wku  = (const float*)d_in[6];
    const float* Wvu  = (const float*)d_in[7];
    const float* Wqr  = (const float*)d_in[8];
    const float* Wkr  = (const float*)d_in[9];
    const float* Wo   = (const float*)d_in[10];
    const float* bo   = (const float*)d_in[11];
    float* out = (float*)d_out;

    float *qlat, *kvlat, *qnew, *knew, *vbuf, *attn, *qrt, *krt;
    float *rinq, *rink, *rWqd, *rWkvd, *rWqu, *rWqr, *rWku, *rWvu, *rWkr, *rWo;
    cudaGetSymbolAddress((void**)&qlat,  g_qlat);
    cudaGetSymbolAddress((void**)&kvlat, g_kvlat);
    cudaGetSymbolAddress((void**)&qnew,  g_qnew);
    cudaGetSymbolAddress((void**)&knew,  g_knew);
    cudaGetSymbolAddress((void**)&vbuf,  g_v);
    cudaGetSymbolAddress((void**)&attn,  g_attn);
    cudaGetSymbolAddress((void**)&qrt,   g_qrt);
    cudaGetSymbolAddress((void**)&krt,   g_krt);
    cudaGetSymbolAddress((void**)&rinq,  g_rinq);
    cudaGetSymbolAddress((void**)&rink,  g_rink);
    cudaGetSymbolAddress((void**)&rWqd,  g_rWqd);
    cudaGetSymbolAddress((void**)&rWkvd, g_rWkvd);
    cudaGetSymbolAddress((void**)&rWqu,  g_rWqu);
    cudaGetSymbolAddress((void**)&rWqr,  g_rWqr);
    cudaGetSymbolAddress((void**)&rWku,  g_rWku);
    cudaGetSymbolAddress((void**)&rWvu,  g_rWvu);
    cudaGetSymbolAddress((void**)&rWkr,  g_rWkr);
    cudaGetSymbolAddress((void**)&rWo,   g_rWo);

    cudaFuncSetAttribute(tf32gemm,
                         cudaFuncAttributeMaxDynamicSharedMemorySize, GEMM_SMEM_BYTES);
    cudaFuncSetAttribute(mla_attn_tf32,
                         cudaFuncAttributeMaxDynamicSharedMemorySize, ATT_SMEM_BYTES);

    // lazily-created side stream + events (first call is outside capture)
    static cudaStream_t s2 = nullptr;
    static cudaEvent_t evFork = nullptr, evQ = nullptr, evJoin = nullptr;
    if (!s2) {
        cudaStreamCreateWithFlags(&s2, cudaStreamNonBlocking);
        cudaEventCreateWithFlags(&evFork, cudaEventDisableTiming);
        cudaEventCreateWithFlags(&evQ,    cudaEventDisableTiming);
        cudaEventCreateWithFlags(&evJoin, cudaEventDisableTiming);
    }

    // 0) pre-round inputs + weights to tf32 (one pass, stream 0)
    roundmany<<<RPT / 256, 256>>>(
        inq, rinq, ink, rink, Wqd, rWqd, Wkvd, rWkvd, Wqu, rWqu,
        Wqr, rWqr, Wku, rWku, Wvu, rWvu, Wkr, rWkr, Wo, rWo);
    cudaEventRecord(evFork, 0);
    cudaStreamWaitEvent(s2, evFork, 0);

    // ---- stream 0: q-chain part 1 ----
    // 1) q_latent = inputs_q @ Wq_down
    tf32gemm<<<dim3(Q_LATD / 128, ROWS / 128), 256, GEMM_SMEM_BYTES>>>(
        rinq, rWqd, qlat, nullptr, ROWS, Q_LATD, D_MODEL, Q_LATD, 0, 1);
    cudaEventRecord(evQ, 0);
    // 3) q_proj -> q_new[..., 0:128] (head-interleave)
    tf32gemm<<<dim3(D_MODEL / 128, ROWS / 128), 256, GEMM_SMEM_BYTES>>>(
        qlat, rWqu, qnew, nullptr, ROWS, D_MODEL, Q_LATD, 4096, 1, 1);

    // ---- stream s2: k-chain, then q_rope (needs qlat via evQ) ----
    // 2) kv_latent = inputs_k @ Wkv_down
    tf32gemm<<<dim3(KV_LATD / 128, ROWS / 128), 256, GEMM_SMEM_BYTES, s2>>>(
        rink, rWkvd, kvlat, nullptr, ROWS, KV_LATD, D_MODEL, KV_LATD, 0, 1);
    // 6) k_proj -> k_new[..., 0:128] (interleave + kpack)
    tf32gemm<<<dim3(D_MODEL / 128, ROWS / 128), 256, GEMM_SMEM_BYTES, s2>>>(
        kvlat, rWku, knew, nullptr, ROWS, D_MODEL, KV_LATD, 4096, 2, 1);
    // 7) v_proj (vpack)
    tf32gemm<<<dim3(D_MODEL / 128, ROWS / 128), 256, GEMM_SMEM_BYTES, s2>>>(
        kvlat, rWvu, vbuf, nullptr, ROWS, D_MODEL, KV_LATD, D_MODEL, 3, 1);
    // 8) k_rope pre-projection
    tf32gemm<<<dim3(HEAD_DIM / 128, ROWS / 128), 256, GEMM_SMEM_BYTES, s2>>>(
        rink, rWkr, krt, nullptr, ROWS, HEAD_DIM, D_MODEL, HEAD_DIM, 0, 1);
    // 9) rope(k) + broadcast (kpack) -> k_new[..., 128:256]
    rope_k_kernel<<<ROWS, 64, 0, s2>>>(krt, knew);
    // 4) q_rope pre-projection (needs qlat)
    cudaStreamWaitEvent(s2, evQ, 0);
    tf32gemm<<<dim3(D_MODEL / 128, ROWS / 128), 256, GEMM_SMEM_BYTES, s2>>>(
        qlat, rWqr, qrt, nullptr, ROWS, D_MODEL, Q_LATD, D_MODEL, 0, 1);
    // 5) rope(q) -> q_new[..., 128:256]
    rope_q_kernel<<<dim3(4, ROWS), 256, 0, s2>>>(qrt, qnew);
    cudaEventRecord(evJoin, s2);

    // ---- stream 0: join, attention, final ----
    cudaStreamWaitEvent(0, evJoin, 0);
    // 10) causal flash attention (round-10 version)
    mla_attn_tf32<<<dim3(SEQ / BQ, NUM_HEADS, BATCH), 256, ATT_SMEM_BYTES>>>(
        qnew, knew, vbuf, attn);
    // 11) final projection + bias (full precision out)
    tf32gemm<<<dim3(D_MODEL / 128, ROWS / 128), 256, GEMM_SMEM_BYTES>>>(
        attn, rWo, out, bo, ROWS, D_MODEL, D_MODEL, D_MODEL, 0, 0);
}

// round 15
// speedup vs baseline: 1.2477x; 1.0822x over previous
#include <cuda_runtime.h>
#include <math.h>
#include <stdint.h>

#define D_MODEL   2048
#define Q_LATD    1536
#define KV_LATD   512
#define NUM_HEADS 16
#define HEAD_DIM  128
#define BATCH     2
#define SEQ       2048
#define ROWS      (BATCH * SEQ)      // 4096
#define QK_DIM    256                // head_dim(128) + rope(128)

// ---------------- scratch (device globals; no allocation allowed) ----------
__device__ float g_qlat[ROWS * Q_LATD];
__device__ float g_kvlat[ROWS * KV_LATD];
__device__ float g_qnew[(size_t)ROWS * NUM_HEADS * QK_DIM];   // [b,s,h,256] natural
__device__ float g_knew[(size_t)ROWS * NUM_HEADS * QK_DIM];   // [b,s,h,256] k-packed
__device__ float g_v[(size_t)ROWS * D_MODEL];                 // [b,s,h*128] v-packed
__device__ float g_attn[(size_t)ROWS * D_MODEL];
__device__ float g_qrt[(size_t)ROWS * D_MODEL];
__device__ float g_krt[(size_t)ROWS * HEAD_DIM];
// pre-rounded inputs + weights (tf32 bit patterns)
__device__ float g_rinq[(size_t)ROWS * D_MODEL];
__device__ float g_rink[(size_t)ROWS * D_MODEL];
__device__ float g_rWqd[(size_t)D_MODEL * Q_LATD];
__device__ float g_rWkvd[(size_t)D_MODEL * KV_LATD];
__device__ float g_rWqu[(size_t)Q_LATD * D_MODEL];
__device__ float g_rWqr[(size_t)Q_LATD * D_MODEL];
__device__ float g_rWku[(size_t)KV_LATD * D_MODEL];
__device__ float g_rWvu[(size_t)KV_LATD * D_MODEL];
__device__ float g_rWkr[(size_t)D_MODEL * HEAD_DIM];
__device__ float g_rWo[(size_t)D_MODEL * D_MODEL];

// ---------------- helpers --------------------------------------------------
__device__ __forceinline__ uint32_t f2tf(float x) {
    uint32_t u;
    asm("cvt.rna.tf32.f32 %0, %1;" : "=r"(u) : "f"(x));
    return u;
}

__device__ __forceinline__ uint32_t sptr(const void* p) {
    return (uint32_t)__cvta_generic_to_shared(p);
}

__device__ __forceinline__ void mma8(float c[4],
    uint32_t a0, uint32_t a1, uint32_t a2, uint32_t a3,
    uint32_t b0, uint32_t b1)
{
    asm volatile(
        "mma.sync.aligned.m16n8k8.row.col.f32.tf32.tf32.f32 "
        "{%0,%1,%2,%3}, {%4,%5,%6,%7}, {%8,%9}, {%0,%1,%2,%3};\n"
        : "+f"(c[0]), "+f"(c[1]), "+f"(c[2]), "+f"(c[3])
        : "r"(a0), "r"(a1), "r"(a2), "r"(a3), "r"(b0), "r"(b1));
}

__device__ __forceinline__ void ldmx4(uint32_t a[4], uint32_t addr) {
    asm volatile(
        "ldmatrix.sync.aligned.m8n8.x4.shared.b16 {%0,%1,%2,%3}, [%4];"
        : "=r"(a[0]), "=r"(a[1]), "=r"(a[2]), "=r"(a[3]) : "r"(addr));
}

#define CP16(dst, src) \
    asm volatile("cp.async.cg.shared.global [%0], [%1], 16;" :: "r"(dst), "l"(src))
#define CP_COMMIT() asm volatile("cp.async.commit_group;" ::: "memory")
#define CP_WAIT0()  asm volatile("cp.async.wait_group 0;" ::: "memory")

// exp(x) for x <= 0 on the FMA pipe only (no MUFU)
__device__ __forceinline__ float fast_exp(float x) {
    float y  = fmaxf(x * 1.4426950408889634f, -126.0f);
    float tb = y + 12582912.0f;
    float nf = tb - 12582912.0f;
    float u  = (y - nf) * 0.6931471805599453f;
    float p  = fmaf(u, 0.008333334f, 0.041666668f);
    p = fmaf(p, u, 0.16666667f);
    p = fmaf(p, u, 0.5f);
    p = fmaf(p, u, 1.0f);
    p = fmaf(p, u, 1.0f);
    return p * __int_as_float(((int)nf + 127) << 23);
}

// digit-swap within a 16-chunk: stored pos 4t+j holds original t+4j
__device__ __forceinline__ int permk(int k) {
    return (k & ~15) | (((k & 3) << 2) | ((k >> 2) & 3));
}

// ---------------- split pre-round passes (float4 granularity) --------------
// part 1: inq + Wqd (gemm1 deps only)
#define PA1 2097152u
#define PAT 2883584u
__global__ void roundA(const float* s0, float* d0, const float* s1, float* d1)
{
    uint32_t i = blockIdx.x * 256u + threadIdx.x;
    const float* s; float* d; uint32_t off;
    if (i < PA1) { s = s0; d = d0; off = i; }
    else         { s = s1; d = d1; off = i - PA1; }
    float4 v = ((const float4*)s)[off];
    ((uint4*)d)[off] = make_uint4(f2tf(v.x), f2tf(v.y), f2tf(v.z), f2tf(v.w));
}

// part 2: ink, Wkvd, Wqu, Wqr, Wku, Wvu, Wkr, Wo
#define PB1 2097152u
#define PB2 2359296u
#define PB3 3145728u
#define PB4 3932160u
#define PB5 4194304u
#define PB6 4456448u
#define PB7 4521984u
#define PBT 5570560u
__global__ void roundB(
    const float* s0, float* d0, const float* s1, float* d1,
    const float* s2, float* d2, const float* s3, float* d3,
    const float* s4, float* d4, const float* s5, float* d5,
    const float* s6, float* d6, const float* s7, float* d7)
{
    uint32_t i = blockIdx.x * 256u + threadIdx.x;
    const float* s; float* d; uint32_t off;
    if      (i < PB1) { s = s0; d = d0; off = i; }
    else if (i < PB2) { s = s1; d = d1; off = i - PB1; }
    else if (i < PB3) { s = s2; d = d2; off = i - PB2; }
    else if (i < PB4) { s = s3; d = d3; off = i - PB3; }
    else if (i < PB5) { s = s4; d = d4; off = i - PB4; }
    else if (i < PB6) { s = s5; d = d5; off = i - PB5; }
    else if (i < PB7) { s = s6; d = d6; off = i - PB6; }
    else              { s = s7; d = d7; off = i - PB7; }
    float4 v = ((const float4*)s)[off];
    ((uint4*)d)[off] = make_uint4(f2tf(v.x), f2tf(v.y), f2tf(v.z), f2tf(v.w));
}

// ---------------- tf32 GEMM v6: dual-output (column-partitioned) -----------
// C[:, 0:nsplit] = A @ B1 (ldc1, mode1 -> C1); C[:, nsplit:N] = A @ B2 -> C2.
// Per-CTA uniform select; hot loop identical to round-9/10 version.
#define GA16 2560
#define GB16 2176
#define GS_STG (2 * GA16 + 2 * GB16)        // 9472 words per 32-k stage
#define GEMM_SMEM_BYTES (2 * GS_STG * 4)    // 75776 B

__global__ void __launch_bounds__(256, 2) tf32gemm(
    const float* __restrict__ A,
    const float* __restrict__ B1, const float* __restrict__ B2, int nsplit,
    float* __restrict__ C1, float* __restrict__ C2,
    const float* __restrict__ bias,
    int M, int N, int K, int ldc1, int ldc2, int mode1, int mode2, int rnd)
{
    extern __shared__ uint32_t sm[];
    const int tid = threadIdx.x, lane = tid & 31, w = tid >> 5;
    const int g = lane >> 2, t = lane & 3;
    const int wm = (w & 1) * 64, wn = (w >> 1) * 32;
    const int bm = blockIdx.y * 128, bn = blockIdx.x * 128;

    const bool sec = bn >= nsplit;
    const float* B = sec ? B2 : B1;
    float* C = sec ? C2 : C1;
    const int Nl   = sec ? (N - nsplit) : nsplit;
    const int bnl  = sec ? (bn - nsplit) : bn;
    const int ldc  = sec ? ldc2 : ldc1;
    const int mode = sec ? mode2 : mode1;

    const int am = tid >> 1, ak = (tid & 1) * 8;
    const int bk = tid >> 4, bn0 = (tid & 15) * 8;
    const float* Ag = A + (size_t)(bm + am) * K + ak;
    const float* Bg = B + (size_t)bk * Nl + bnl + bn0;

    const uint32_t smb = sptr(sm);
    const uint32_t aStg = smb + ((am * 20 + ak) << 2);
    const uint32_t bStg = smb + ((2 * GA16 + bk * 136 + bn0) << 2);
    const uint32_t aFrag = smb +
        (((wm + (lane & 15)) * 20 + ((lane >> 4) << 2)) << 2);

    float acc[4][4][4];
#pragma unroll
    for (int i = 0; i < 4; i++)
#pragma unroll
        for (int j = 0; j < 4; j++)
#pragma unroll
            for (int e = 0; e < 4; e++) acc[i][j][e] = 0.f;

    const int nk = K >> 5;

    auto issue = [&](int s) {
        const uint32_t so = (uint32_t)((s & 1) * GS_STG) << 2;
        const float* Ap = Ag + s * 32;
        CP16(aStg + so, Ap);
        CP16(aStg + so + 16, Ap + 4);
        CP16(aStg + so + (GA16 << 2), Ap + 16);
        CP16(aStg + so + (GA16 << 2) + 16, Ap + 20);
        const float* Bp = Bg + (size_t)s * 32 * Nl;
        CP16(bStg + so, Bp);
        CP16(bStg + so + 16, Bp + 4);
        const float* Bp1 = Bp + (size_t)16 * Nl;
        CP16(bStg + so + (GB16 << 2), Bp1);
        CP16(bStg + so + (GB16 << 2) + 16, Bp1 + 4);
    };

    issue(0); CP_COMMIT();

    for (int kt = 0; kt < nk; kt++) {
        CP_WAIT0();
        __syncthreads();
        if (kt + 1 < nk) { issue(kt + 1); CP_COMMIT(); }

        const uint32_t stg = (uint32_t)((kt & 1) * GS_STG);
        const uint32_t aS = aFrag + (stg << 2);
        const uint32_t* Bsl = sm + stg + 2 * GA16;

#pragma unroll
        for (int sb = 0; sb < 2; sb++) {
            const uint32_t aSb = aS + ((uint32_t)(sb * GA16) << 2);
            const uint32_t* Bs = Bsl + sb * GB16;
#pragma unroll
            for (int ks = 0; ks < 2; ks++) {
                const int k0 = ks * 8;
                uint32_t af[4][4], bf[4][2];
#pragma unroll
                for (int mt = 0; mt < 4; mt++)
                    ldmx4(af[mt], aSb + mt * 1280 + ks * 32);
#pragma unroll
                for (int nt = 0; nt < 4; nt++) {
                    const int n = wn + nt * 8 + g;
                    bf[nt][0] = Bs[(k0 + t) * 136 + n];
                    bf[nt][1] = Bs[(k0 + t + 4) * 136 + n];
                }
#pragma unroll
                for (int mt = 0; mt < 4; mt++)
#pragma unroll
                    for (int nt = 0; nt < 4; nt++)
                        mma8(acc[mt][nt], af[mt][0], af[mt][1], af[mt][2], af[mt][3],
                             bf[nt][0], bf[nt][1]);
            }
        }
    }

#pragma unroll
    for (int mt = 0; mt < 4; mt++) {
#pragma unroll
        for (int nt = 0; nt < 4; nt++) {
            const int r = bm + wm + mt * 16 + g;
            const int c = bnl + wn + nt * 8 + 2 * t;
#pragma unroll
            for (int e = 0; e < 4; e++) {
                const int rr = r + ((e >> 1) << 3);
                const int cc = c + (e & 1);
                float v = acc[mt][nt][e];
                if (bias) v += bias[cc];
                if (rnd) v = __uint_as_float(f2tf(v));
                int oc;
                if (mode == 0)      oc = cc;
                else if (mode == 1) oc = ((cc >> 7) << 8) + (cc & 127);
                else if (mode == 2) oc = ((cc >> 7) << 8) + permk(cc & 127);
                else {
                    int ww = cc & 127;
                    oc = (cc & ~127) + ((ww & 7) << 4) + (ww >> 3);
                }
                C[(size_t)rr * ldc + oc] = v;
            }
        }
    }
}

// ---------------- rope on q (full 2048 dims) -> q_new[...,128:256] ---------
__global__ void rope_q_kernel(const float* __restrict__ in, float* __restrict__ qnew)
{
    int j = blockIdx.x * blockDim.x + threadIdx.x;
    int row = blockIdx.y;
    if (j >= 1024) return;
    int pos = row & (SEQ - 1);
    float inv = powf(10000.0f, -(float)j * (1.0f / 1024.0f));
    float ang = (float)pos * inv;
    float sn, cs;
    sincosf(ang, &sn, &cs);
    float x1 = in[(size_t)row * 2048 + j];
    float x2 = in[(size_t)row * 2048 + j + 1024];
    float o1 = __uint_as_float(f2tf(x1 * cs - x2 * sn));
    float o2 = __uint_as_float(f2tf(x2 * cs + x1 * sn));
    int c1 = j, c2 = j + 1024;
    qnew[(size_t)row * 4096 + (c1 >> 7) * 256 + (c1 & 127) + 128] = o1;
    qnew[(size_t)row * 4096 + (c2 >> 7) * 256 + (c2 & 127) + 128] = o2;
}

// ---------------- rope on k + broadcast to all heads (k-packed) ------------
__global__ void rope_k_kernel(const float* __restrict__ in, float* __restrict__ knew)
{
    int j = threadIdx.x;          // 0..63
    int row = blockIdx.x;
    int pos = row & (SEQ - 1);
    float inv = powf(10000.0f, -(float)j * (1.0f / 64.0f));
    float ang = (float)pos * inv;
    float sn, cs;
    sincosf(ang, &sn, &cs);
    float x1 = in[(size_t)row * 128 + j];
    float x2 = in[(size_t)row * 128 + j + 64];
    float o1 = __uint_as_float(f2tf(x1 * cs - x2 * sn));
    float o2 = __uint_as_float(f2tf(x2 * cs + x1 * sn));
    const int p1 = permk(128 + j);
    const int p2 = permk(128 + j + 64);
    float* base = knew + (size_t)row * 4096;
#pragma unroll
    for (int h = 0; h < NUM_HEADS; h++) {
        base[h * 256 + p1] = o1;
        base[h * 256 + p2] = o2;
    }
}

// ---------------- flash attention v5 (round-10 + heavy-first) --------------
#define BQ   128
#define BK2  32
#define SQH  132   // % 32 == 4  -> conflict-free ldmatrix rows
#define SKS  272   // % 32 == 16 -> conflict-free LDS.128 K frags
#define SVS  132   // % 32 == 4  -> conflict-free LDS.128 V frags
#define SPS  36
#define QH_WORDS (BQ * SQH)          // 16896
#define K_WORDS  (2 * BK2 * SKS)     // 17408 (>= QH_WORDS: doubles as Q-lo scratch)
#define V_WORDS  (2 * BK2 * SVS)     // 8448
#define P_WORDS  (BQ * SPS)          // 4608
#define ATT_SMEM_BYTES ((QH_WORDS + K_WORDS + V_WORDS + P_WORDS) * 4)  // 189440

__global__ void __launch_bounds__(256, 1) mla_attn_tf32(
    const float* __restrict__ Qn, const float* __restrict__ Kn,
    const float* __restrict__ Vp, float* __restrict__ Op)
{
    extern __shared__ uint32_t sw[];
    uint32_t* sQh = sw;                  // [128][132] Q dims 128..255
    uint32_t* sK  = sQh + QH_WORDS;      // [2][32][272] (scratch for Q-lo at init)
    uint32_t* sV  = sK + K_WORDS;        // [2][32][132]
    uint32_t* sP  = sV + V_WORDS;        // [128][36]

    const int tid = threadIdx.x, lane = tid & 31, w = tid >> 5;
    const int g = lane >> 2, t = lane & 3;
    const int qt = (int)gridDim.x - 1 - (int)blockIdx.x;   // heavy CTAs first
    const int h = blockIdx.y, b = blockIdx.z;
    const int q0 = w * 16;

    const uint32_t qhAddr = sptr(sQh) +
        (((q0 + (lane & 15)) * SQH + ((lane >> 4) << 2)) << 2);
    const uint32_t qloAddr = sptr(sK) +
        (((q0 + (lane & 15)) * SQH + ((lane >> 4) << 2)) << 2);
    const uint32_t pAddr = sptr(sP) +
        (((q0 + (lane & 15)) * SPS + ((lane >> 4) << 2)) << 2);
    const uint32_t kBase = sptr(sK), vBase = sptr(sV);

    // ---- stage Q: lo half into K-region scratch, hi half into sQh ----
    {
        const int r = tid >> 1, d0 = (tid & 1) * 64;
        const float* qp = Qn + (((size_t)(b * SEQ + qt * BQ + r)) * NUM_HEADS + h) * QK_DIM;
        const float sc = 0.0625f;   // 1/sqrt(2*HEAD_DIM) = 2^-4 exact
        uint32_t* dlo = (uint32_t*)sK + r * SQH + d0;
        uint32_t* dhi = sQh + r * SQH + d0;
#pragma unroll
        for (int j = 0; j < 16; j++) {
            float4 v = *(const float4*)(qp + d0 + j * 4);
            *(uint4*)(dlo + j * 4) = make_uint4(
                __float_as_uint(v.x * sc), __float_as_uint(v.y * sc),
                __float_as_uint(v.z * sc), __float_as_uint(v.w * sc));
            float4 u = *(const float4*)(qp + 128 + d0 + j * 4);
            *(uint4*)(dhi + j * 4) = make_uint4(
                __float_as_uint(u.x * sc), __float_as_uint(u.y * sc),
                __float_as_uint(u.z * sc), __float_as_uint(u.w * sc));
        }
    }
    __syncthreads();

    // hoist Q-lo fragments (dims 0..127) into registers
    uint32_t qreg[16][4];
#pragma unroll
    for (int c = 0; c < 8; c++) {
        ldmx4(qreg[2 * c],     qloAddr + c * 64);
        ldmx4(qreg[2 * c + 1], qloAddr + c * 64 + 32);
    }
    __syncthreads();   // all warps done reading scratch before K prefetch

    const int sr  = tid >> 3;          // staging row 0..31
    const int ks8 = (tid & 7) * 32;    // K seg: 32 words
    const int vs8 = (tid & 7) * 16;    // V seg: 16 words

    const int ntiles = 4 * qt + 4;

    auto prefetchKV = [&](int tile) {
        const int slot = tile & 1;
        const float* kp = Kn + (((size_t)(b * SEQ + tile * BK2 + sr)) * NUM_HEADS + h) * QK_DIM + ks8;
        uint32_t kd = kBase + ((slot * BK2 * SKS + sr * SKS + ks8) << 2);
#pragma unroll
        for (int j = 0; j < 8; j++) CP16(kd + j * 16, kp + j * 4);
        const float* vp = Vp + ((size_t)(b * SEQ + tile * BK2 + sr)) * D_MODEL + h * HEAD_DIM + vs8;
        uint32_t vd = vBase + ((slot * BK2 * SVS + sr * SVS + vs8) << 2);
#pragma unroll
        for (int j = 0; j < 4; j++) CP16(vd + j * 16, vp + j * 4);
    };

    prefetchKV(0); CP_COMMIT();

    float oacc[16][4];
#pragma unroll
    for (int dt = 0; dt < 16; dt++)
#pragma unroll
        for (int e = 0; e < 4; e++) oacc[dt][e] = 0.f;
    float mA = -3e38f, mB = -3e38f, lA = 0.f, lB = 0.f;

    for (int tt = 0; tt < ntiles; tt++) {
        CP_WAIT0();
        __syncthreads();
        if (tt + 1 < ntiles) { prefetchKV(tt + 1); CP_COMMIT(); }

        const uint32_t* sKb = sK + (tt & 1) * BK2 * SKS;
        const uint32_t* sVb = sV + (tt & 1) * BK2 * SVS;

        // S = Q @ K^T  (16 q-rows x 32 keys per warp)
        float sacc[4][4];
#pragma unroll
        for (int j = 0; j < 4; j++)
#pragma unroll
            for (int e = 0; e < 4; e++) sacc[j][e] = 0.f;

        // dims 0..127 from registers
#pragma unroll
        for (int c = 0; c < 8; c++) {
#pragma unroll
            for (int j = 0; j < 4; j++) {
                const uint4 kf = *(const uint4*)&sKb[(j * 8 + g) * SKS + c * 16 + t * 4];
                mma8(sacc[j], qreg[2*c][0], qreg[2*c][1], qreg[2*c][2], qreg[2*c][3],
                     kf.x, kf.y);
                mma8(sacc[j], qreg[2*c+1][0], qreg[2*c+1][1], qreg[2*c+1][2], qreg[2*c+1][3],
                     kf.z, kf.w);
            }
        }
        // dims 128..255 streamed from compact sQh
#pragma unroll
        for (int c = 0; c < 8; c++) {
            uint32_t a0[4], a1[4];
            ldmx4(a0, qhAddr + c * 64);
            ldmx4(a1, qhAddr + c * 64 + 32);
#pragma unroll
            for (int j = 0; j < 4; j++) {
                const uint4 kf = *(const uint4*)&sKb[(j * 8 + g) * SKS + (c + 8) * 16 + t * 4];
                mma8(sacc[j], a0[0], a0[1], a0[2], a0[3], kf.x, kf.y);
                mma8(sacc[j], a1[0], a1[1], a1[2], a1[3], kf.z, kf.w);
            }
        }

        if (tt >= 4 * qt) {   // diagonal-region masking
            const int kb = tt * BK2 + 2 * t;
            const int qA = qt * BQ + q0 + g, qB = qA + 8;
#pragma unroll
            for (int j = 0; j < 4; j++) {
                int k0g = kb + j * 8;
                if (k0g     > qA) sacc[j][0] = -3e38f;
                if (k0g + 1 > qA) sacc[j][1] = -3e38f;
                if (k0g     > qB) sacc[j][2] = -3e38f;
                if (k0g + 1 > qB) sacc[j][3] = -3e38f;
            }
        }

        // online softmax (rows owned by quads)
        float rmA = -3e38f, rmB = -3e38f;
#pragma unroll
        for (int j = 0; j < 4; j++) {
            rmA = fmaxf(rmA, fmaxf(sacc[j][0], sacc[j][1]));
            rmB = fmaxf(rmB, fmaxf(sacc[j][2], sacc[j][3]));
        }
        rmA = fmaxf(rmA, __shfl_xor_sync(0xffffffffu, rmA, 1));
        rmA = fmaxf(rmA, __shfl_xor_sync(0xffffffffu, rmA, 2));
        rmB = fmaxf(rmB, __shfl_xor_sync(0xffffffffu, rmB, 1));
        rmB = fmaxf(rmB, __shfl_xor_sync(0xffffffffu, rmB, 2));
        float mnA = fmaxf(mA, rmA), mnB = fmaxf(mB, rmB);
        float aAl = fast_exp(mA - mnA), aBl = fast_exp(mB - mnB);
        mA = mnA; mB = mnB;

        float lsA = 0.f, lsB = 0.f;
        uint32_t* pA = sP + (q0 + g) * SPS;
        uint32_t* pB = pA + 8 * SPS;
#pragma unroll
        for (int j = 0; j < 4; j++) {
            uint32_t p0 = f2tf(fast_exp(sacc[j][0] - mnA));
            uint32_t p1 = f2tf(fast_exp(sacc[j][1] - mnA));
            uint32_t p2 = f2tf(fast_exp(sacc[j][2] - mnB));
            uint32_t p3 = f2tf(fast_exp(sacc[j][3] - mnB));
            lsA += __uint_as_float(p0) + __uint_as_float(p1);
            lsB += __uint_as_float(p2) + __uint_as_float(p3);
            pA[j * 8 + 2 * t] = p0; pA[j * 8 + 2 * t + 1] = p1;
            pB[j * 8 + 2 * t] = p2; pB[j * 8 + 2 * t + 1] = p3;
        }
        lsA += __shfl_xor_sync(0xffffffffu, lsA, 1);
        lsA += __shfl_xor_sync(0xffffffffu, lsA, 2);
        lsB += __shfl_xor_sync(0xffffffffu, lsB, 1);
        lsB += __shfl_xor_sync(0xffffffffu, lsB, 2);
        lA = lA * aAl + lsA;
        lB = lB * aBl + lsB;

#pragma unroll
        for (int dt = 0; dt < 16; dt++) {
            oacc[dt][0] *= aAl; oacc[dt][1] *= aAl;
            oacc[dt][2] *= aBl; oacc[dt][3] *= aBl;
        }
        __syncwarp();

        // O += P @ V  (V packed: one LDS.128 = 4 consecutive dt operands)
#pragma unroll
        for (int k0 = 0; k0 < BK2; k0 += 8) {
            uint32_t p[4];
            ldmx4(p, pAddr + k0 * 4);
            const uint32_t* vr0 = sVb + (k0 + t) * SVS + g * 16;
            const uint32_t* vr1 = sVb + (k0 + t + 4) * SVS + g * 16;
#pragma unroll
            for (int u = 0; u < 4; u++) {
                const uint4 v0 = *(const uint4*)&vr0[u * 4];
                const uint4 v1 = *(const uint4*)&vr1[u * 4];
                mma8(oacc[u * 4 + 0], p[0], p[1], p[2], p[3], v0.x, v1.x);
                mma8(oacc[u * 4 + 1], p[0], p[1], p[2], p[3], v0.y, v1.y);
                mma8(oacc[u * 4 + 2], p[0], p[1], p[2], p[3], v0.z, v1.z);
                mma8(oacc[u * 4 + 3], p[0], p[1], p[2], p[3], v0.w, v1.w);
            }
        }
    }

    // normalize + write (tf32-rounded: feeds final cp.async GEMM)
    float iA = 1.f / lA, iB = 1.f / lB;
    float* oA = Op + ((size_t)(b * SEQ + qt * BQ + q0 + g)) * D_MODEL + h * HEAD_DIM;
    float* oB = oA + (size_t)8 * D_MODEL;
#pragma unroll
    for (int dt = 0; dt < 16; dt++) {
        int c = dt * 8 + 2 * t;
        *(uint2*)(oA + c) = make_uint2(f2tf(oacc[dt][0] * iA), f2tf(oacc[dt][1] * iA));
        *(uint2*)(oB + c) = make_uint2(f2tf(oacc[dt][2] * iB), f2tf(oacc[dt][3] * iB));
    }
}

// ---------------------------------------------------------------------------
extern "C" void kernel_launch(void* const* d_in, const int* in_sizes, int n_in,
                              void* d_out, int out_size)
{
    const float* inq  = (const float*)d_in[0];
    const float* ink  = (const float*)d_in[1];
    const float* Wqd  = (const float*)d_in[3];
    const float* Wkvd = (const float*)d_in[4];
    const float* Wqu  = (const float*)d_in[5];
    const float* Wku  = (const float*)d_in[6];
    const float* Wvu  = (const float*)d_in[7];
    const float* Wqr  = (const float*)d_in[8];
    const float* Wkr  = (const float*)d_in[9];
    const float* Wo   = (const float*)d_in[10];
    const float* bo   = (const float*)d_in[11];
    float* out = (float*)d_out;

    float *qlat, *kvlat, *qnew, *knew, *vbuf, *attn, *qrt, *krt;
    float *rinq, *rink, *rWqd, *rWkvd, *rWqu, *rWqr, *rWku, *rWvu, *rWkr, *rWo;
    cudaGetSymbolAddress((void**)&qlat,  g_qlat);
    cudaGetSymbolAddress((void**)&kvlat, g_kvlat);
    cudaGetSymbolAddress((void**)&qnew,  g_qnew);
    cudaGetSymbolAddress((void**)&knew,  g_knew);
    cudaGetSymbolAddress((void**)&vbuf,  g_v);
    cudaGetSymbolAddress((void**)&attn,  g_attn);
    cudaGetSymbolAddress((void**)&qrt,   g_qrt);
    cudaGetSymbolAddress((void**)&krt,   g_krt);
    cudaGetSymbolAddress((void**)&rinq,  g_rinq);
    cudaGetSymbolAddress((void**)&rink,  g_rink);
    cudaGetSymbolAddress((void**)&rWqd,  g_rWqd);
    cudaGetSymbolAddress((void**)&rWkvd, g_rWkvd);
    cudaGetSymbolAddress((void**)&rWqu,  g_rWqu);
    cudaGetSymbolAddress((void**)&rWqr,  g_rWqr);
    cudaGetSymbolAddress((void**)&rWku,  g_rWku);
    cudaGetSymbolAddress((void**)&rWvu,  g_rWvu);
    cudaGetSymbolAddress((void**)&rWkr,  g_rWkr);
    cudaGetSymbolAddress((void**)&rWo,   g_rWo);

    cudaFuncSetAttribute(tf32gemm,
                         cudaFuncAttributeMaxDynamicSharedMemorySize, GEMM_SMEM_BYTES);
    cudaFuncSetAttribute(mla_attn_tf32,
                         cudaFuncAttributeMaxDynamicSharedMemorySize, ATT_SMEM_BYTES);

    // lazily-created side stream + events (first call is outside capture)
    static cudaStream_t s2 = nullptr;
    static cudaEvent_t evFork = nullptr, evQ = nullptr, evP2 = nullptr, evJoin = nullptr;
    if (!s2) {
        cudaStreamCreateWithFlags(&s2, cudaStreamNonBlocking);
        cudaEventCreateWithFlags(&evFork, cudaEventDisableTiming);
        cudaEventCreateWithFlags(&evQ,    cudaEventDisableTiming);
        cudaEventCreateWithFlags(&evP2,   cudaEventDisableTiming);
        cudaEventCreateWithFlags(&evJoin, cudaEventDisableTiming);
    }

    // ---- fork s2 from the capturing origin stream FIRST ----
    cudaEventRecord(evFork, 0);
    cudaStreamWaitEvent(s2, evFork, 0);

    // ---- stream s2: part2 prepass, k-chain ----
    roundB<<<PBT / 256, 256, 0, s2>>>(
        ink, rink, Wkvd, rWkvd, Wqu, rWqu, Wqr, rWqr,
        Wku, rWku, Wvu, rWvu, Wkr, rWkr, Wo, rWo);
    cudaEventRecord(evP2, s2);
    // kv_latent + k_rope pre-projection (dual: N = 512 + 128)
    tf32gemm<<<dim3((KV_LATD + HEAD_DIM) / 128, ROWS / 128), 256, GEMM_SMEM_BYTES, s2>>>(
        rink, rWkvd, rWkr, KV_LATD, kvlat, krt, nullptr,
        ROWS, KV_LATD + HEAD_DIM, D_MODEL, KV_LATD, HEAD_DIM, 0, 0, 1);
    // k_proj + v_proj (dual: N = 2048 + 2048)
    tf32gemm<<<dim3(2 * D_MODEL / 128, ROWS / 128), 256, GEMM_SMEM_BYTES, s2>>>(
        kvlat, rWku, rWvu, D_MODEL, knew, vbuf, nullptr,
        ROWS, 2 * D_MODEL, KV_LATD, 4096, D_MODEL, 2, 3, 1);
    // rope(k) + broadcast (kpack)
    rope_k_kernel<<<ROWS, 64, 0, s2>>>(krt, knew);

    // ---- stream 0: part1 prepass, q-chain ----
    roundA<<<PAT / 256, 256>>>(inq, rinq, Wqd, rWqd);
    // q_latent
    tf32gemm<<<dim3(Q_LATD / 128, ROWS / 128), 256, GEMM_SMEM_BYTES>>>(
        rinq, rWqd, rWqd, Q_LATD, qlat, qlat, nullptr,
        ROWS, Q_LATD, D_MODEL, Q_LATD, Q_LATD, 0, 0, 1);
    cudaEventRecord(evQ, 0);
    // q_proj -> q_new[..., 0:128] (head-interleave; needs rWqu from part2)
    cudaStreamWaitEvent(0, evP2, 0);
    tf32gemm<<<dim3(D_MODEL / 128, ROWS / 128), 256, GEMM_SMEM_BYTES>>>(
        qlat, rWqu, rWqu, D_MODEL, qnew, qnew, nullptr,
        ROWS, D_MODEL, Q_LATD, 4096, 4096, 1, 1, 1);

    // ---- stream s2: q_rope (needs qlat) ----
    cudaStreamWaitEvent(s2, evQ, 0);
    tf32gemm<<<dim3(D_MODEL / 128, ROWS / 128), 256, GEMM_SMEM_BYTES, s2>>>(
        qlat, rWqr, rWqr, D_MODEL, qrt, qrt, nullptr,
        ROWS, D_MODEL, Q_LATD, D_MODEL, D_MODEL, 0, 0, 1);
    rope_q_kernel<<<dim3(4, ROWS), 256, 0, s2>>>(qrt, qnew);
    cudaEventRecord(evJoin, s2);

    // ---- stream 0: join, attention, final ----
    cudaStreamWaitEvent(0, evJoin, 0);
    mla_attn_tf32<<<dim3(SEQ / BQ, NUM_HEADS, BATCH), 256, ATT_SMEM_BYTES>>>(
        qnew, knew, vbuf, attn);
    tf32gemm<<<dim3(D_MODEL / 128, ROWS / 128), 256, GEMM_SMEM_BYTES>>>(
        attn, rWo, rWo, D_MODEL, out, out, bo,
        ROWS, D_MODEL, D_MODEL, D_MODEL, D_MODEL, 0, 0, 0);
}